// round 5
// baseline (speedup 1.0000x reference)
#include <cuda_runtime.h>
#include <math.h>

// Shapes are fixed by the problem.
#define Bn 16
#define Cn 128
#define Ln 2048

// ---------------------------------------------------------------------------
// helpers: tf32 conversion + m16n8k8 tf32 mma
// ---------------------------------------------------------------------------
__device__ __forceinline__ unsigned f2tf32(float x) {
    unsigned r;
    asm("cvt.rna.tf32.f32 %0, %1;" : "=r"(r) : "f"(x));
    return r;
}

__device__ __forceinline__ void mma_tf32(float* c, const unsigned* a, const unsigned* b) {
    asm volatile(
        "mma.sync.aligned.m16n8k8.row.col.f32.tf32.tf32.f32 "
        "{%0,%1,%2,%3}, {%4,%5,%6,%7}, {%8,%9}, {%0,%1,%2,%3};"
        : "+f"(c[0]), "+f"(c[1]), "+f"(c[2]), "+f"(c[3])
        : "r"(a[0]), "r"(a[1]), "r"(a[2]), "r"(a[3]), "r"(b[0]), "r"(b[1]));
}

// ---------------------------------------------------------------------------
// K1: energy = Q^T K, scaled + log(mask+1e-6), written TRANSPOSED as logits
//     into attT[b][k][q]  (attT region of d_out doubles as scratch).
// Tile: 128(q) x 128(k), BK=16 over C=128. 256 threads = 8 warps (4x2).
// ---------------------------------------------------------------------------
__global__ void __launch_bounds__(256, 2)
qk_logits_kernel(const float* __restrict__ Q, const float* __restrict__ Km,
                 const float* __restrict__ mask, float* __restrict__ attT) {
    extern __shared__ float sm[];
    float* As = sm;             // [16][132] tf32 bits (A = Q^T tile, [k][q])
    float* Bs = sm + 16 * 132;  // [16][132]            (B = K tile,  [k][n])
    float* lm = sm + 128 * 132; // [128] log-mask per k column

    const int b  = blockIdx.z;
    const int q0 = blockIdx.y * 128;
    const int k0 = blockIdx.x * 128;
    const int tid = threadIdx.x;
    const float* Qb = Q  + (size_t)b * Cn * Ln;
    const float* Kb = Km + (size_t)b * Cn * Ln;

    if (tid < 128) lm[tid] = logf(mask[b * Ln + k0 + tid] + 1e-6f);

    const int warp = tid >> 5, lane = tid & 31;
    const int wm = warp >> 1, wn = warp & 1;  // warp grid 4(M) x 2(N)
    const int g = lane >> 2, tg = lane & 3;

    float acc[2][8][4];
#pragma unroll
    for (int i = 0; i < 2; i++)
#pragma unroll
        for (int j = 0; j < 8; j++)
#pragma unroll
            for (int v = 0; v < 4; v++) acc[i][j][v] = 0.f;

    for (int kc = 0; kc < Cn; kc += 16) {
        // stage: 16 rows (channel) x 128 cols, both operands, tf32-rounded
#pragma unroll
        for (int i = 0; i < 2; i++) {
            int idx = tid + i * 256;          // 0..511
            int r   = idx >> 5;               // 0..15 channel row
            int c4  = (idx & 31) << 2;        // float4 column
            float4 va = *reinterpret_cast<const float4*>(Qb + (size_t)(kc + r) * Ln + q0 + c4);
            unsigned* da = reinterpret_cast<unsigned*>(As + r * 132 + c4);
            da[0] = f2tf32(va.x); da[1] = f2tf32(va.y); da[2] = f2tf32(va.z); da[3] = f2tf32(va.w);
            float4 vb = *reinterpret_cast<const float4*>(Kb + (size_t)(kc + r) * Ln + k0 + c4);
            unsigned* db = reinterpret_cast<unsigned*>(Bs + r * 132 + c4);
            db[0] = f2tf32(vb.x); db[1] = f2tf32(vb.y); db[2] = f2tf32(vb.z); db[3] = f2tf32(vb.w);
        }
        __syncthreads();
#pragma unroll
        for (int ks = 0; ks < 2; ks++) {
            int kb = ks * 8;
            unsigned a[2][4];
#pragma unroll
            for (int mt = 0; mt < 2; mt++) {
                int m = wm * 32 + mt * 16 + g;
                a[mt][0] = __float_as_uint(As[(kb + tg) * 132 + m]);
                a[mt][1] = __float_as_uint(As[(kb + tg) * 132 + m + 8]);
                a[mt][2] = __float_as_uint(As[(kb + tg + 4) * 132 + m]);
                a[mt][3] = __float_as_uint(As[(kb + tg + 4) * 132 + m + 8]);
            }
#pragma unroll
            for (int nt = 0; nt < 8; nt++) {
                int n = wn * 64 + nt * 8 + g;
                unsigned bf[2];
                bf[0] = __float_as_uint(Bs[(kb + tg) * 132 + n]);
                bf[1] = __float_as_uint(Bs[(kb + tg + 4) * 132 + n]);
                mma_tf32(acc[0][nt], a[0], bf);
                mma_tf32(acc[1][nt], a[1], bf);
            }
        }
        __syncthreads();
    }

    // epilogue: transpose through smem (st[k][q]), then coalesced row writes
    const float scale = 0.088388347648318447f;  // 1/sqrt(128)
    float* st = sm;  // [128][132] — overlaps As/Bs, safe after last sync
#pragma unroll
    for (int mt = 0; mt < 2; mt++) {
        int q = wm * 32 + mt * 16 + g;
#pragma unroll
        for (int nt = 0; nt < 8; nt++) {
            int k = wn * 64 + nt * 8 + 2 * tg;
            st[k * 132 + q]           = acc[mt][nt][0] * scale;
            st[(k + 1) * 132 + q]     = acc[mt][nt][1] * scale;
            st[k * 132 + q + 8]       = acc[mt][nt][2] * scale;
            st[(k + 1) * 132 + q + 8] = acc[mt][nt][3] * scale;
        }
    }
    __syncthreads();
    float* dst = attT + (size_t)b * Ln * Ln + (size_t)k0 * Ln + q0;
#pragma unroll
    for (int i = 0; i < 16; i++) {
        int idx = tid + i * 256;   // 0..4095 float4 slots
        int row = idx >> 5;        // k row 0..127
        int c4  = (idx & 31) << 2; // q offset
        float l = lm[row];
        const float* s4 = st + row * 132 + c4;
        float4 v;
        v.x = s4[0] + l; v.y = s4[1] + l; v.z = s4[2] + l; v.w = s4[3] + l;
        *reinterpret_cast<float4*>(dst + (size_t)row * Ln + c4) = v;
    }
}

// ---------------------------------------------------------------------------
// K2: in-place softmax over k (rows of the LOGICAL attention, columns of attT)
//     + post-softmax multiplicative mask. Block owns 8 q's: reads/writes the
//     8-float (32B, one sector) chunk of every attT row -> fully sector-efficient.
// ---------------------------------------------------------------------------
__global__ void __launch_bounds__(256)
softmax_kernel(const float* __restrict__ mask, float* __restrict__ attT) {
    extern __shared__ float smem2[];       // [8][2048] + inv[8]
    float* inv = smem2 + 8 * 2048;
    const int b  = blockIdx.y;
    const int q0 = blockIdx.x * 8;
    const int tid = threadIdx.x;
    float* base = attT + (size_t)b * Ln * Ln + q0;

#pragma unroll
    for (int i = 0; i < 8; i++) {
        int k = tid + i * 256;
        const float* p = base + (size_t)k * Ln;
        float4 v0 = *reinterpret_cast<const float4*>(p);
        float4 v1 = *reinterpret_cast<const float4*>(p + 4);
        smem2[0 * 2048 + k] = v0.x; smem2[1 * 2048 + k] = v0.y;
        smem2[2 * 2048 + k] = v0.z; smem2[3 * 2048 + k] = v0.w;
        smem2[4 * 2048 + k] = v1.x; smem2[5 * 2048 + k] = v1.y;
        smem2[6 * 2048 + k] = v1.z; smem2[7 * 2048 + k] = v1.w;
    }
    __syncthreads();

    const int warp = tid >> 5, lane = tid & 31;
    float* row = smem2 + warp * 2048;       // warp j handles query q0+j
    float m = -1e30f;
    for (int i = lane; i < 2048; i += 32) m = fmaxf(m, row[i]);
#pragma unroll
    for (int o = 16; o > 0; o >>= 1) m = fmaxf(m, __shfl_xor_sync(0xffffffffu, m, o));
    float s = 0.f;
    for (int i = lane; i < 2048; i += 32) {
        float e = __expf(row[i] - m);
        row[i] = e;
        s += e;
    }
#pragma unroll
    for (int o = 16; o > 0; o >>= 1) s += __shfl_xor_sync(0xffffffffu, s, o);
    if (lane == 0) inv[warp] = 1.0f / s;
    __syncthreads();

#pragma unroll
    for (int i = 0; i < 8; i++) {
        int k = tid + i * 256;
        float mk = mask[b * Ln + k];
        float4 v0, v1;
        v0.x = smem2[0 * 2048 + k] * inv[0] * mk;
        v0.y = smem2[1 * 2048 + k] * inv[1] * mk;
        v0.z = smem2[2 * 2048 + k] * inv[2] * mk;
        v0.w = smem2[3 * 2048 + k] * inv[3] * mk;
        v1.x = smem2[4 * 2048 + k] * inv[4] * mk;
        v1.y = smem2[5 * 2048 + k] * inv[5] * mk;
        v1.z = smem2[6 * 2048 + k] * inv[6] * mk;
        v1.w = smem2[7 * 2048 + k] * inv[7] * mk;
        float* p = base + (size_t)k * Ln;
        *reinterpret_cast<float4*>(p)     = v0;
        *reinterpret_cast<float4*>(p + 4) = v1;
    }
}

// ---------------------------------------------------------------------------
// K3: out[b] = V[b] (128 x 2048) * attT[b] (2048 x 2048)
// Tile: M=128 (full C), N=64, BK=16. 256 threads = 8 warps (4x2), warp 32x32.
// ---------------------------------------------------------------------------
__global__ void __launch_bounds__(256, 2)
av_kernel(const float* __restrict__ V, const float* __restrict__ attT,
          float* __restrict__ out) {
    extern __shared__ float sm3[];
    float* As = sm3;             // [128][20]  V tile, [c][k]
    float* Bs = sm3 + 128 * 20;  // [16][68]   attT tile, [k][q]
    const int b  = blockIdx.y;
    const int q0 = blockIdx.x * 64;
    const int tid = threadIdx.x;
    const float* Vb = V    + (size_t)b * Cn * Ln;
    const float* Tb = attT + (size_t)b * Ln * Ln;

    const int warp = tid >> 5, lane = tid & 31;
    const int wm = warp >> 1, wn = warp & 1;
    const int g = lane >> 2, tg = lane & 3;

    float acc[2][4][4];
#pragma unroll
    for (int i = 0; i < 2; i++)
#pragma unroll
        for (int j = 0; j < 4; j++)
#pragma unroll
            for (int v = 0; v < 4; v++) acc[i][j][v] = 0.f;

    for (int kk = 0; kk < Ln; kk += 16) {
        // stage A: 128 rows (c) x 16 k
#pragma unroll
        for (int i = 0; i < 2; i++) {
            int idx = tid + i * 256;
            int r   = idx >> 2;          // c row
            int c4  = (idx & 3) << 2;    // k offset
            float4 v = *reinterpret_cast<const float4*>(Vb + (size_t)r * Ln + kk + c4);
            unsigned* d = reinterpret_cast<unsigned*>(As + r * 20 + c4);
            d[0] = f2tf32(v.x); d[1] = f2tf32(v.y); d[2] = f2tf32(v.z); d[3] = f2tf32(v.w);
        }
        // stage B: 16 rows (k) x 64 q
        {
            int r  = tid >> 4;
            int c4 = (tid & 15) << 2;
            float4 v = *reinterpret_cast<const float4*>(Tb + (size_t)(kk + r) * Ln + q0 + c4);
            unsigned* d = reinterpret_cast<unsigned*>(Bs + r * 68 + c4);
            d[0] = f2tf32(v.x); d[1] = f2tf32(v.y); d[2] = f2tf32(v.z); d[3] = f2tf32(v.w);
        }
        __syncthreads();
#pragma unroll
        for (int ks = 0; ks < 2; ks++) {
            int kb = ks * 8;
            unsigned a[2][4];
#pragma unroll
            for (int mt = 0; mt < 2; mt++) {
                int m = wm * 32 + mt * 16 + g;
                a[mt][0] = __float_as_uint(As[m * 20 + kb + tg]);
                a[mt][1] = __float_as_uint(As[(m + 8) * 20 + kb + tg]);
                a[mt][2] = __float_as_uint(As[m * 20 + kb + tg + 4]);
                a[mt][3] = __float_as_uint(As[(m + 8) * 20 + kb + tg + 4]);
            }
#pragma unroll
            for (int nt = 0; nt < 4; nt++) {
                int n = wn * 32 + nt * 8 + g;
                unsigned bf[2];
                bf[0] = __float_as_uint(Bs[(kb + tg) * 68 + n]);
                bf[1] = __float_as_uint(Bs[(kb + tg + 4) * 68 + n]);
                mma_tf32(acc[0][nt], a[0], bf);
                mma_tf32(acc[1][nt], a[1], bf);
            }
        }
        __syncthreads();
    }

    float* ob = out + (size_t)b * Cn * Ln;
#pragma unroll
    for (int mt = 0; mt < 2; mt++) {
        int c = wm * 32 + mt * 16 + g;
#pragma unroll
        for (int nt = 0; nt < 4; nt++) {
            int q = q0 + wn * 32 + nt * 8 + 2 * tg;
            float2 v0; v0.x = acc[mt][nt][0]; v0.y = acc[mt][nt][1];
            *reinterpret_cast<float2*>(ob + (size_t)c * Ln + q) = v0;
            float2 v1; v1.x = acc[mt][nt][2]; v1.y = acc[mt][nt][3];
            *reinterpret_cast<float2*>(ob + (size_t)(c + 8) * Ln + q) = v1;
        }
    }
}

// ---------------------------------------------------------------------------
// launch
// ---------------------------------------------------------------------------
extern "C" void kernel_launch(void* const* d_in, const int* in_sizes, int n_in,
                              void* d_out, int out_size) {
    const float* Q    = (const float*)d_in[0];
    const float* K    = (const float*)d_in[1];
    const float* V    = (const float*)d_in[2];
    const float* mask = (const float*)d_in[3];

    float* out  = (float*)d_out;                      // [B, C, L]
    float* attT = out + (size_t)Bn * Cn * Ln;         // [B, L, L] (also logit scratch)

    const int SMEM_K1 = (128 * 132 + 128) * 4;        // 68,096 B
    const int SMEM_K2 = (8 * 2048 + 8) * 4;           // 65,568 B
    const int SMEM_K3 = (128 * 20 + 16 * 68) * 4;     // 14,592 B

    cudaFuncSetAttribute(qk_logits_kernel, cudaFuncAttributeMaxDynamicSharedMemorySize, SMEM_K1);
    cudaFuncSetAttribute(softmax_kernel,   cudaFuncAttributeMaxDynamicSharedMemorySize, SMEM_K2);

    dim3 g1(Ln / 128, Ln / 128, Bn);   // (16, 16, 16)
    qk_logits_kernel<<<g1, 256, SMEM_K1>>>(Q, K, mask, attT);

    dim3 g2(Ln / 8, Bn);               // (256, 16)
    softmax_kernel<<<g2, 256, SMEM_K2>>>(mask, attT);

    dim3 g3(Ln / 64, Bn);              // (32, 16)
    av_kernel<<<g3, 256, SMEM_K3>>>(V, attT, out);
}

// round 6
// speedup vs baseline: 1.4858x; 1.4858x over previous
#include <cuda_runtime.h>
#include <math.h>

#define Bn 16
#define Cn 128
#define Ln 2048

// smem pads (floats): operands read as [kdim][x] by mma frags want pad%32==8;
// operands read as [m][kdim] want pad%32==4.
#define PAD  136   // Ks (QK A), Qs (QK B), Ps (AV B)
#define PADV 132   // Vs (AV A)

// smem layout in floats
#define QS_OFF 0
#define KS_OFF 17408            // 128*136
#define PS_OFF 34816
#define LM_OFF 52224
#define SR_OFF 54272            // 4*128 partial sums
#define SI_OFF 54784            // 128 inv sums
#define SMEM_FLOATS 54912       // 219,648 bytes

__device__ __forceinline__ unsigned f2tf32(float x) {
    unsigned r;
    asm("cvt.rna.tf32.f32 %0, %1;" : "=r"(r) : "f"(x));
    return r;
}

__device__ __forceinline__ void mma_tf32(float* c, const unsigned* a, const unsigned* b) {
    asm volatile(
        "mma.sync.aligned.m16n8k8.row.col.f32.tf32.tf32.f32 "
        "{%0,%1,%2,%3}, {%4,%5,%6,%7}, {%8,%9}, {%0,%1,%2,%3};"
        : "+f"(c[0]), "+f"(c[1]), "+f"(c[2]), "+f"(c[3])
        : "r"(a[0]), "r"(a[1]), "r"(a[2]), "r"(a[3]), "r"(b[0]), "r"(b[1]));
}

// One block = (batch b, 128-query strip). Does QK + exp + softmax-sum +
// normalize + mask + attT write + AV, with attT doubling as the unnormalized
// exp buffer between pass 1 and pass 2.
__global__ void __launch_bounds__(256, 1)
fused_attn_kernel(const float* __restrict__ Q, const float* __restrict__ Kg,
                  const float* __restrict__ V, const float* __restrict__ mask,
                  float* __restrict__ out, float* __restrict__ attT) {
    extern __shared__ float sm[];
    float* Qs   = sm + QS_OFF;   // [128 c][PAD]  tf32 Q tile (persistent)
    float* Ks   = sm + KS_OFF;   // [128 c][PAD]  tf32 K tile / V tile (PADV)
    float* Ps   = sm + PS_OFF;   // [128 k][PAD]  tf32 normalized P tile
    float* lm   = sm + LM_OFF;   // [2048] log(mask + 1e-6)
    float* sred = sm + SR_OFF;
    float* sinv = sm + SI_OFF;

    const int b   = blockIdx.y;
    const int q0  = blockIdx.x * 128;
    const int tid = threadIdx.x;
    const int warp = tid >> 5, lane = tid & 31;
    const int wm = warp >> 1, wn = warp & 1;    // 4(m) x 2(n) warp grid
    const int g = lane >> 2, tg = lane & 3;

    const float* Qb = Q  + (size_t)b * Cn * Ln;
    const float* Kb = Kg + (size_t)b * Cn * Ln;
    const float* Vb = V  + (size_t)b * Cn * Ln;
    float* Tb = attT + (size_t)b * Ln * Ln;

    for (int i = tid; i < Ln; i += 256) lm[i] = __logf(mask[b * Ln + i] + 1e-6f);

    // stage Q tile [c=128][q=128] once
#pragma unroll
    for (int i = 0; i < 16; i++) {
        int idx = tid + i * 256;
        int r = idx >> 5, c4 = (idx & 31) << 2;
        float4 v = *reinterpret_cast<const float4*>(Qb + (size_t)r * Ln + q0 + c4);
        unsigned* d = reinterpret_cast<unsigned*>(Qs + r * PAD + c4);
        d[0] = f2tf32(v.x); d[1] = f2tf32(v.y); d[2] = f2tf32(v.z); d[3] = f2tf32(v.w);
    }
    __syncthreads();

    const float scale = 0.08838834764831845f;   // 1/sqrt(128)
    float s_part[16];
#pragma unroll
    for (int j = 0; j < 16; j++) s_part[j] = 0.f;

    // ------------------- pass 1: QK, exp, write unnormalized p -------------
    for (int kt = 0; kt < 16; kt++) {
        const int k0 = kt * 128;
#pragma unroll
        for (int i = 0; i < 16; i++) {
            int idx = tid + i * 256;
            int r = idx >> 5, c4 = (idx & 31) << 2;
            float4 v = *reinterpret_cast<const float4*>(Kb + (size_t)r * Ln + k0 + c4);
            unsigned* d = reinterpret_cast<unsigned*>(Ks + r * PAD + c4);
            d[0] = f2tf32(v.x); d[1] = f2tf32(v.y); d[2] = f2tf32(v.z); d[3] = f2tf32(v.w);
        }
        __syncthreads();

        float acc[2][8][4];
#pragma unroll
        for (int i = 0; i < 2; i++)
#pragma unroll
            for (int j = 0; j < 8; j++)
#pragma unroll
                for (int v = 0; v < 4; v++) acc[i][j][v] = 0.f;

#pragma unroll
        for (int cc = 0; cc < Cn; cc += 8) {
            unsigned a[2][4];
#pragma unroll
            for (int mt = 0; mt < 2; mt++) {
                int m = wm * 32 + mt * 16 + g;
                a[mt][0] = __float_as_uint(Ks[(cc + tg) * PAD + m]);
                a[mt][1] = __float_as_uint(Ks[(cc + tg) * PAD + m + 8]);
                a[mt][2] = __float_as_uint(Ks[(cc + tg + 4) * PAD + m]);
                a[mt][3] = __float_as_uint(Ks[(cc + tg + 4) * PAD + m + 8]);
            }
#pragma unroll
            for (int nt = 0; nt < 8; nt++) {
                int n = wn * 64 + nt * 8 + g;
                unsigned bb[2];
                bb[0] = __float_as_uint(Qs[(cc + tg) * PAD + n]);
                bb[1] = __float_as_uint(Qs[(cc + tg + 4) * PAD + n]);
                mma_tf32(acc[0][nt], a[0], bb);
                mma_tf32(acc[1][nt], a[1], bb);
            }
        }

        // epilogue: p = exp(scale*e + logmask), store, accumulate row sums
#pragma unroll
        for (int mt = 0; mt < 2; mt++) {
            int krow = k0 + wm * 32 + mt * 16 + g;
            float l0 = lm[krow], l1 = lm[krow + 8];
            float* row0 = Tb + (size_t)krow * Ln + q0 + wn * 64;
            float* row1 = row0 + (size_t)8 * Ln;
#pragma unroll
            for (int nt = 0; nt < 8; nt++) {
                int qoff = nt * 8 + 2 * tg;
                float p0 = __expf(fmaf(acc[mt][nt][0], scale, l0));
                float p1 = __expf(fmaf(acc[mt][nt][1], scale, l0));
                float p2 = __expf(fmaf(acc[mt][nt][2], scale, l1));
                float p3 = __expf(fmaf(acc[mt][nt][3], scale, l1));
                s_part[2 * nt]     += p0 + p2;
                s_part[2 * nt + 1] += p1 + p3;
                *reinterpret_cast<float2*>(row0 + qoff) = make_float2(p0, p1);
                *reinterpret_cast<float2*>(row1 + qoff) = make_float2(p2, p3);
            }
        }
        __syncthreads();
    }

    // ------------------- softmax denominators ------------------------------
#pragma unroll
    for (int j = 0; j < 16; j++) {
        float v = s_part[j];
        v += __shfl_xor_sync(0xffffffffu, v, 4);
        v += __shfl_xor_sync(0xffffffffu, v, 8);
        v += __shfl_xor_sync(0xffffffffu, v, 16);
        s_part[j] = v;
    }
    if (g == 0) {
#pragma unroll
        for (int j = 0; j < 16; j++) {
            int ql = wn * 64 + (j >> 1) * 8 + 2 * tg + (j & 1);
            sred[wm * 128 + ql] = s_part[j];
        }
    }
    __syncthreads();
    if (tid < 128) {
        float s = sred[tid] + sred[128 + tid] + sred[256 + tid] + sred[384 + tid];
        sinv[tid] = 1.0f / s;
    }
    __syncthreads();

    // ------------------- pass 2: normalize+mask+write attT, AV mma ---------
    float oacc[2][8][4];
#pragma unroll
    for (int i = 0; i < 2; i++)
#pragma unroll
        for (int j = 0; j < 8; j++)
#pragma unroll
            for (int v = 0; v < 4; v++) oacc[i][j][v] = 0.f;

    for (int kt = 15; kt >= 0; kt--) {          // reverse: L2-friendly
        const int k0 = kt * 128;
        // reload p, scale by inv*mask, final attT write, stash tf32 in Ps
#pragma unroll
        for (int i = 0; i < 16; i++) {
            int idx = tid + i * 256;
            int r = idx >> 5, c4 = (idx & 31) << 2;
            int krow = k0 + r;
            float mk = lm[krow] > -1.0f ? 1.0f : 0.0f;
            float* gp = Tb + (size_t)krow * Ln + q0 + c4;
            float4 v = *reinterpret_cast<const float4*>(gp);
            float4 iv = *reinterpret_cast<const float4*>(sinv + c4);
            v.x *= iv.x * mk; v.y *= iv.y * mk;
            v.z *= iv.z * mk; v.w *= iv.w * mk;
            __stcs(reinterpret_cast<float4*>(gp), v);
            unsigned* d = reinterpret_cast<unsigned*>(Ps + r * PAD + c4);
            d[0] = f2tf32(v.x); d[1] = f2tf32(v.y); d[2] = f2tf32(v.z); d[3] = f2tf32(v.w);
        }
        // stage V tile [c=128][k=128] into the Ks buffer (pad PADV)
#pragma unroll
        for (int i = 0; i < 16; i++) {
            int idx = tid + i * 256;
            int r = idx >> 5, c4 = (idx & 31) << 2;
            float4 v = *reinterpret_cast<const float4*>(Vb + (size_t)r * Ln + k0 + c4);
            unsigned* d = reinterpret_cast<unsigned*>(Ks + r * PADV + c4);
            d[0] = f2tf32(v.x); d[1] = f2tf32(v.y); d[2] = f2tf32(v.z); d[3] = f2tf32(v.w);
        }
        __syncthreads();

#pragma unroll
        for (int kk = 0; kk < 128; kk += 8) {
            unsigned a[2][4];
#pragma unroll
            for (int mt = 0; mt < 2; mt++) {
                int m = wm * 32 + mt * 16 + g;
                a[mt][0] = __float_as_uint(Ks[m * PADV + kk + tg]);
                a[mt][1] = __float_as_uint(Ks[(m + 8) * PADV + kk + tg]);
                a[mt][2] = __float_as_uint(Ks[m * PADV + kk + tg + 4]);
                a[mt][3] = __float_as_uint(Ks[(m + 8) * PADV + kk + tg + 4]);
            }
#pragma unroll
            for (int nt = 0; nt < 8; nt++) {
                int n = wn * 64 + nt * 8 + g;
                unsigned bb[2];
                bb[0] = __float_as_uint(Ps[(kk + tg) * PAD + n]);
                bb[1] = __float_as_uint(Ps[(kk + tg + 4) * PAD + n]);
                mma_tf32(oacc[0][nt], a[0], bb);
                mma_tf32(oacc[1][nt], a[1], bb);
            }
        }
        __syncthreads();
    }

    // ------------------- write out[b][c][q] --------------------------------
    float* ob = out + (size_t)b * Cn * Ln;
#pragma unroll
    for (int mt = 0; mt < 2; mt++) {
        int c = wm * 32 + mt * 16 + g;
#pragma unroll
        for (int nt = 0; nt < 8; nt++) {
            int q = q0 + wn * 64 + nt * 8 + 2 * tg;
            __stcs(reinterpret_cast<float2*>(ob + (size_t)c * Ln + q),
                   make_float2(oacc[mt][nt][0], oacc[mt][nt][1]));
            __stcs(reinterpret_cast<float2*>(ob + (size_t)(c + 8) * Ln + q),
                   make_float2(oacc[mt][nt][2], oacc[mt][nt][3]));
        }
    }
}

extern "C" void kernel_launch(void* const* d_in, const int* in_sizes, int n_in,
                              void* d_out, int out_size) {
    const float* Q    = (const float*)d_in[0];
    const float* K    = (const float*)d_in[1];
    const float* V    = (const float*)d_in[2];
    const float* mask = (const float*)d_in[3];

    float* out  = (float*)d_out;                  // [B, C, L]
    float* attT = out + (size_t)Bn * Cn * Ln;     // [B, Lk, Lq]

    const int SMEM = SMEM_FLOATS * 4;             // 219,648 B
    cudaFuncSetAttribute(fused_attn_kernel,
                         cudaFuncAttributeMaxDynamicSharedMemorySize, SMEM);

    dim3 grid(Ln / 128, Bn);                      // (16, 16) = 256 blocks
    fused_attn_kernel<<<grid, 256, SMEM>>>(Q, K, V, mask, out, attT);
}